// round 1
// baseline (speedup 1.0000x reference)
#include <cuda_runtime.h>
#include <math.h>

#define NN 50000
#define EE 800000
#define LLAYERS 3
#define DD 64
#define GG 512
#define GDIM 128

// ---------------- scratch (static __device__, no allocs) ----------------
__device__ int   g_deg[NN];
__device__ int   g_fill[NN];
__device__ int   g_rowptr[NN + 1];
__device__ int   g_src[EE];
__device__ float g_ea[EE];
__device__ float g_Q[NN * DD];
__device__ float g_K[NN * DD];
__device__ float g_V[NN * DD];
__device__ float g_S[NN * DD];   // skip = x @ Wskip + bskip
__device__ float g_h[NN * DD];   // layer output (pre-relu)
__device__ float g_pool[GG * DD];
__device__ int   g_cnt[GG];

// ---------------- utility ----------------
__global__ void zero_scratch_kernel() {
    int idx = blockIdx.x * blockDim.x + threadIdx.x;
    int stride = gridDim.x * blockDim.x;
    for (int i = idx; i < NN; i += stride) { g_deg[i] = 0; g_fill[i] = 0; }
    for (int i = idx; i < GG * DD; i += stride) g_pool[i] = 0.f;
    for (int i = idx; i < GG; i += stride) g_cnt[i] = 0;
}

__global__ void hist_kernel(const int* __restrict__ dst) {
    int e = blockIdx.x * blockDim.x + threadIdx.x;
    if (e < EE) atomicAdd(&g_deg[dst[e]], 1);
}

// single-block exclusive scan over g_deg -> g_rowptr
__global__ void scan_kernel() {
    __shared__ int sh[1024];
    __shared__ int carry;
    int t = threadIdx.x;
    if (t == 0) carry = 0;
    __syncthreads();
    for (int base = 0; base < NN; base += 1024) {
        int i = base + t;
        int v = (i < NN) ? g_deg[i] : 0;
        sh[t] = v;
        __syncthreads();
        for (int off = 1; off < 1024; off <<= 1) {
            int tmp = (t >= off) ? sh[t - off] : 0;
            __syncthreads();
            sh[t] += tmp;
            __syncthreads();
        }
        if (i < NN) g_rowptr[i] = carry + sh[t] - v;
        __syncthreads();
        if (t == 0) carry += sh[1023];
        __syncthreads();
    }
    if (t == 0) g_rowptr[NN] = carry;
}

__global__ void scatter_kernel(const int* __restrict__ src, const int* __restrict__ dst,
                               const float* __restrict__ ea) {
    int e = blockIdx.x * blockDim.x + threadIdx.x;
    if (e >= EE) return;
    int d = dst[e];
    int pos = g_rowptr[d] + atomicAdd(&g_fill[d], 1);
    g_src[pos] = src[e];
    g_ea[pos]  = ea[e];
}

// ---------------- fused QKV+Skip projection ----------------
// out cols: [0:64)=Q [64:128)=K [128:192)=V [192:256)=Skip
#define TN 32
__global__ __launch_bounds__(256) void gemm_qkvs(
    const float* __restrict__ X, int useX, int reluIn,
    const float* __restrict__ Wq, const float* __restrict__ bq,
    const float* __restrict__ Wk, const float* __restrict__ bk,
    const float* __restrict__ Wv, const float* __restrict__ bv,
    const float* __restrict__ Wsk, const float* __restrict__ bsk)
{
    extern __shared__ float sh[];
    float* Wsm = sh;                 // [64][256]
    float* Xsm = sh + 64 * 256;      // [TN][64]
    int tid = threadIdx.x;

    for (int i = tid; i < 64 * 64; i += 256) {
        int d = i >> 6, j = i & 63;
        Wsm[d * 256 + j]       = Wq[i];
        Wsm[d * 256 + 64 + j]  = Wk[i];
        Wsm[d * 256 + 128 + j] = Wv[i];
        Wsm[d * 256 + 192 + j] = Wsk[i];
    }
    int nodeBase = blockIdx.x * TN;
    for (int i = tid; i < TN * 64; i += 256) {
        int n = i >> 6, d = i & 63;
        int gn = nodeBase + n;
        float v = 0.f;
        if (gn < NN) v = useX ? X[gn * 64 + d] : g_h[gn * 64 + d];
        if (reluIn) v = fmaxf(v, 0.f);
        Xsm[n * 64 + d] = v;
    }
    __syncthreads();

    int cg = tid & 31;   // column group -> cols cg + 32*c
    int ng = tid >> 5;   // node group  -> nodes ng*4 + n
    float acc[4][8];
#pragma unroll
    for (int n = 0; n < 4; n++)
#pragma unroll
        for (int c = 0; c < 8; c++) acc[n][c] = 0.f;

#pragma unroll 4
    for (int d = 0; d < 64; d++) {
        float w[8];
#pragma unroll
        for (int c = 0; c < 8; c++) w[c] = Wsm[d * 256 + cg + 32 * c];
#pragma unroll
        for (int n = 0; n < 4; n++) {
            float xv = Xsm[(ng * 4 + n) * 64 + d];
#pragma unroll
            for (int c = 0; c < 8; c++) acc[n][c] = fmaf(xv, w[c], acc[n][c]);
        }
    }

#pragma unroll
    for (int n = 0; n < 4; n++) {
        int gn = nodeBase + ng * 4 + n;
        if (gn >= NN) continue;
#pragma unroll
        for (int c = 0; c < 8; c++) {
            int j = cg + 32 * c;
            int mat = j >> 6;
            int col = j & 63;
            float bias, *dstp;
            if (mat == 0)      { bias = bq[col];  dstp = g_Q; }
            else if (mat == 1) { bias = bk[col];  dstp = g_K; }
            else if (mat == 2) { bias = bv[col];  dstp = g_V; }
            else               { bias = bsk[col]; dstp = g_S; }
            dstp[gn * 64 + col] = acc[n][c] + bias;
        }
    }
}

// ---------------- attention: warp per node, CSR gather, online softmax ----------------
__global__ __launch_bounds__(256) void attn_kernel(const float* __restrict__ We_l,
                                                   float* __restrict__ dout, int toDout)
{
    int warpId = (blockIdx.x * blockDim.x + threadIdx.x) >> 5;
    int lane = threadIdx.x & 31;
    if (warpId >= NN) return;
    int i = warpId;

    float qa = g_Q[i * 64 + lane];
    float qb = g_Q[i * 64 + 32 + lane];
    float wea = We_l[lane];
    float web = We_l[32 + lane];

    float mA = -1e30f, mB = -1e30f;
    float lA = 0.f, lB = 0.f;
    float accA = 0.f, accB = 0.f;

    int beg = g_rowptr[i], end = g_rowptr[i + 1];
    for (int p = beg; p < end; p++) {
        int s = g_src[p];
        float ea = g_ea[p];
        float ka = g_K[s * 64 + lane]      + ea * wea;
        float kb = g_K[s * 64 + 32 + lane] + ea * web;
        float va = g_V[s * 64 + lane]      + ea * wea;
        float vb = g_V[s * 64 + 32 + lane] + ea * web;

        float dA = qa * ka;
        float dB = qb * kb;
#pragma unroll
        for (int off = 8; off >= 1; off >>= 1) {
            dA += __shfl_xor_sync(0xffffffffu, dA, off);
            dB += __shfl_xor_sync(0xffffffffu, dB, off);
        }
        dA *= 0.25f;   // 1/sqrt(C), C=16
        dB *= 0.25f;

        float mA2 = fmaxf(mA, dA);
        float cA  = __expf(mA - mA2);
        float pA  = __expf(dA - mA2);
        accA = accA * cA + pA * va;
        lA   = lA * cA + pA;
        mA   = mA2;

        float mB2 = fmaxf(mB, dB);
        float cB  = __expf(mB - mB2);
        float pB  = __expf(dB - mB2);
        accB = accB * cB + pB * vb;
        lB   = lB * cB + pB;
        mB   = mB2;
    }

    float oA = (lA > 0.f) ? accA / lA : 0.f;
    float oB = (lB > 0.f) ? accB / lB : 0.f;
    float rA = oA + g_S[i * 64 + lane];
    float rB = oB + g_S[i * 64 + 32 + lane];
    if (toDout) {
        dout[i * 64 + lane]      = rA;
        dout[i * 64 + 32 + lane] = rB;
    } else {
        g_h[i * 64 + lane]      = rA;
        g_h[i * 64 + 32 + lane] = rB;
    }
}

// ---------------- pooling ----------------
__global__ void pool_kernel(const float* __restrict__ h, const int* __restrict__ batch) {
    int idx = blockIdx.x * blockDim.x + threadIdx.x;
    if (idx >= NN * DD) return;
    int n = idx >> 6, c = idx & 63;
    atomicAdd(&g_pool[batch[n] * DD + c], h[n * DD + c]);
}
__global__ void cnt_kernel(const int* __restrict__ batch) {
    int n = blockIdx.x * blockDim.x + threadIdx.x;
    if (n < NN) atomicAdd(&g_cnt[batch[n]], 1);
}

// ---------------- graph MLP head ----------------
__global__ void mlp_kernel(const float* __restrict__ W1, const float* __restrict__ b1,
                           const float* __restrict__ W2, const float* __restrict__ b2,
                           const float* __restrict__ W3, const float* __restrict__ b3,
                           float* __restrict__ out)
{
    int g = blockIdx.x;
    int t = threadIdx.x; // 128
    __shared__ float gsh[64], h1[64], h2[16];
    if (t < 64) {
        float c = fmaxf((float)g_cnt[g], 1.f);
        gsh[t] = g_pool[g * 64 + t] / c;
    }
    __syncthreads();
    if (t < 64) {
        float a = b1[t];
#pragma unroll 8
        for (int d = 0; d < 64; d++) a = fmaf(gsh[d], W1[d * 64 + t], a);
        h1[t] = fmaxf(a, 0.f);
    }
    __syncthreads();
    if (t < 16) {
        float a = b2[t];
#pragma unroll 8
        for (int d = 0; d < 64; d++) a = fmaf(h1[d], W2[d * 16 + t], a);
        h2[t] = fmaxf(a, 0.f);
    }
    __syncthreads();
    {
        float a = b3[t];
#pragma unroll
        for (int d = 0; d < 16; d++) a = fmaf(h2[d], W3[d * 128 + t], a);
        out[g * 128 + t] = a;
    }
}

// ---------------- launch ----------------
extern "C" void kernel_launch(void* const* d_in, const int* in_sizes, int n_in,
                              void* d_out, int out_size)
{
    // Resolve input ordering: metadata may be dict-order (edge_index at slot 2)
    // or reference-signature-order (edge_index at slot 17). Distinguish by size.
    const int* ei;
    const int* batch;
    int iW;
    if (in_sizes[2] == 2 * EE) {          // dict order: x, ea, edge_index, batch, Wq...
        ei    = (const int*)d_in[2];
        batch = (const int*)d_in[3];
        iW = 4;
    } else {                               // signature order: x, ea, Wq..., edge_index, batch
        ei    = (const int*)d_in[17];
        batch = (const int*)d_in[18];
        iW = 2;
    }
    const float* x    = (const float*)d_in[0];
    const float* ea   = (const float*)d_in[1];
    const float* Wq   = (const float*)d_in[iW + 0];
    const float* bq   = (const float*)d_in[iW + 1];
    const float* Wk   = (const float*)d_in[iW + 2];
    const float* bk   = (const float*)d_in[iW + 3];
    const float* Wv   = (const float*)d_in[iW + 4];
    const float* bv   = (const float*)d_in[iW + 5];
    const float* We   = (const float*)d_in[iW + 6];
    const float* Wsk  = (const float*)d_in[iW + 7];
    const float* bsk  = (const float*)d_in[iW + 8];
    const float* W1   = (const float*)d_in[iW + 9];
    const float* b1   = (const float*)d_in[iW + 10];
    const float* W2   = (const float*)d_in[iW + 11];
    const float* b2   = (const float*)d_in[iW + 12];
    const float* W3   = (const float*)d_in[iW + 13];
    const float* b3   = (const float*)d_in[iW + 14];

    const int* srcIdx = ei;
    const int* dstIdx = ei + EE;
    float* out = (float*)d_out;

    static bool attr_set = false;
    if (!attr_set) {
        cudaFuncSetAttribute(gemm_qkvs, cudaFuncAttributeMaxDynamicSharedMemorySize,
                             (64 * 256 + TN * 64) * sizeof(float));
        attr_set = true;
    }

    // CSR build (once per launch; reused by all 3 layers)
    zero_scratch_kernel<<<256, 256>>>();
    hist_kernel<<<(EE + 255) / 256, 256>>>(dstIdx);
    scan_kernel<<<1, 1024>>>();
    scatter_kernel<<<(EE + 255) / 256, 256>>>(srcIdx, dstIdx, ea);

    size_t smem = (64 * 256 + TN * 64) * sizeof(float);
    int gemmGrid = (NN + TN - 1) / TN;
    int attnGrid = (NN * 32 + 255) / 256;

    for (int l = 0; l < LLAYERS; l++) {
        int useX   = (l == 0) ? 1 : 0;
        int reluIn = (l == 0) ? 0 : 1;
        gemm_qkvs<<<gemmGrid, 256, smem>>>(
            x, useX, reluIn,
            Wq + l * DD * DD, bq + l * DD,
            Wk + l * DD * DD, bk + l * DD,
            Wv + l * DD * DD, bv + l * DD,
            Wsk + l * DD * DD, bsk + l * DD);
        int toDout = (l == LLAYERS - 1) ? 1 : 0;
        attn_kernel<<<attnGrid, 256>>>(We + l * DD, out, toDout);
    }

    // pool over final node embeddings (already in d_out) + MLP head
    pool_kernel<<<(NN * DD + 255) / 256, 256>>>(out, batch);
    cnt_kernel<<<(NN + 255) / 256, 256>>>(batch);
    mlp_kernel<<<GG, 128>>>(W1, b1, W2, b2, W3, b3, out + (size_t)NN * DD);
}

// round 2
// speedup vs baseline: 1.1613x; 1.1613x over previous
#include <cuda_runtime.h>
#include <math.h>

#define NN 50000
#define EE 800000
#define LLAYERS 3
#define DD 64
#define GG 512
#define GDIM 128

// ---------------- scratch (static __device__, no allocs) ----------------
__device__ int   g_deg[NN];
__device__ int   g_fill[NN];
__device__ int   g_rowptr[NN + 1];
__device__ int   g_src[EE];
__device__ float g_ea[EE];
__device__ float g_Q[NN * DD];
__device__ float g_KV[NN * 2 * DD];   // per node: [0:64)=K, [64:128)=V (one 512B row)
__device__ float g_S[NN * DD];        // skip = x @ Wskip + bskip
__device__ float g_h[NN * DD];        // layer output (pre-relu)
__device__ float g_pool[GG * DD];
__device__ int   g_cnt[GG];

// ---------------- packed fp32x2 FMA (sm_100+) ----------------
__device__ __forceinline__ float2 ffma2(float2 x, float2 w, float2 a) {
    float2 r;
    asm("fma.rn.f32x2 %0, %1, %2, %3;"
        : "=l"(reinterpret_cast<unsigned long long&>(r))
        : "l"(reinterpret_cast<unsigned long long&>(x)),
          "l"(reinterpret_cast<unsigned long long&>(w)),
          "l"(reinterpret_cast<unsigned long long&>(a)));
    return r;
}

// ---------------- utility ----------------
__global__ void zero_scratch_kernel() {
    int idx = blockIdx.x * blockDim.x + threadIdx.x;
    int stride = gridDim.x * blockDim.x;
    for (int i = idx; i < NN; i += stride) { g_deg[i] = 0; g_fill[i] = 0; }
    for (int i = idx; i < GG * DD; i += stride) g_pool[i] = 0.f;
    for (int i = idx; i < GG; i += stride) g_cnt[i] = 0;
}

__global__ void hist_kernel(const int* __restrict__ dst) {
    int e = blockIdx.x * blockDim.x + threadIdx.x;
    if (e < EE) atomicAdd(&g_deg[dst[e]], 1);
}

// raking scan: 1024 threads, each owns 49 consecutive elements. ~20 barriers total.
__global__ void scan_kernel() {
    __shared__ int sh[1024];
    int t = threadIdx.x;
    const int PER = (NN + 1023) / 1024;  // 49
    int base = t * PER;
    int sum = 0;
#pragma unroll 7
    for (int i = 0; i < PER; i++) {
        int idx = base + i;
        if (idx < NN) sum += g_deg[idx];
    }
    sh[t] = sum;
    __syncthreads();
    for (int off = 1; off < 1024; off <<= 1) {
        int v = (t >= off) ? sh[t - off] : 0;
        __syncthreads();
        sh[t] += v;
        __syncthreads();
    }
    int run = sh[t] - sum;  // exclusive prefix
    for (int i = 0; i < PER; i++) {
        int idx = base + i;
        if (idx < NN) {
            g_rowptr[idx] = run;
            run += g_deg[idx];
        }
    }
    if (t == 1023) g_rowptr[NN] = sh[1023];
}

__global__ void scatter_kernel(const int* __restrict__ src, const int* __restrict__ dst,
                               const float* __restrict__ ea) {
    int e = blockIdx.x * blockDim.x + threadIdx.x;
    if (e >= EE) return;
    int d = dst[e];
    int pos = g_rowptr[d] + atomicAdd(&g_fill[d], 1);
    g_src[pos] = src[e];
    g_ea[pos]  = ea[e];
}

// ---------------- fused QKV+Skip projection, FFMA2 packed ----------------
// logical out cols: [0:64)=Q [64:128)=K [128:192)=V [192:256)=Skip
// thread (cg = tid&31, ng = tid>>5) computes nodes ng*4..+3, col pairs (2cg, 2cg+1)+64c
#define TN 32
__global__ __launch_bounds__(256) void gemm_qkvs(
    const float* __restrict__ X, int useX, int reluIn,
    const float* __restrict__ Wq, const float* __restrict__ bq,
    const float* __restrict__ Wk, const float* __restrict__ bk,
    const float* __restrict__ Wv, const float* __restrict__ bv,
    const float* __restrict__ Wsk, const float* __restrict__ bsk)
{
    extern __shared__ float sh[];
    float* Wsm = sh;                 // [64][256]
    float* Xsm = sh + 64 * 256;      // [TN][64]
    int tid = threadIdx.x;

    for (int i = tid; i < 64 * 64; i += 256) {
        int d = i >> 6, j = i & 63;
        Wsm[d * 256 + j]       = Wq[i];
        Wsm[d * 256 + 64 + j]  = Wk[i];
        Wsm[d * 256 + 128 + j] = Wv[i];
        Wsm[d * 256 + 192 + j] = Wsk[i];
    }
    int nodeBase = blockIdx.x * TN;
    for (int i = tid; i < TN * 64; i += 256) {
        int n = i >> 6, d = i & 63;
        int gn = nodeBase + n;
        float v = 0.f;
        if (gn < NN) v = useX ? X[gn * 64 + d] : g_h[gn * 64 + d];
        if (reluIn) v = fmaxf(v, 0.f);
        Xsm[n * 64 + d] = v;
    }
    __syncthreads();

    int cg = tid & 31;   // col pair base = 2*cg
    int ng = tid >> 5;   // nodes ng*4 + n
    float2 acc[4][4];
#pragma unroll
    for (int n = 0; n < 4; n++)
#pragma unroll
        for (int c = 0; c < 4; c++) acc[n][c] = make_float2(0.f, 0.f);

#pragma unroll 4
    for (int d = 0; d < 64; d++) {
        float2 w[4];
#pragma unroll
        for (int c = 0; c < 4; c++)
            w[c] = *reinterpret_cast<const float2*>(&Wsm[d * 256 + 2 * cg + 64 * c]);
#pragma unroll
        for (int n = 0; n < 4; n++) {
            float xv = Xsm[(ng * 4 + n) * 64 + d];
            float2 xx = make_float2(xv, xv);
#pragma unroll
            for (int c = 0; c < 4; c++) acc[n][c] = ffma2(xx, w[c], acc[n][c]);
        }
    }

    int colp = 2 * cg;
    float2 bQ = make_float2(bq[colp],  bq[colp + 1]);
    float2 bK = make_float2(bk[colp],  bk[colp + 1]);
    float2 bV = make_float2(bv[colp],  bv[colp + 1]);
    float2 bS = make_float2(bsk[colp], bsk[colp + 1]);
#pragma unroll
    for (int n = 0; n < 4; n++) {
        int gn = nodeBase + ng * 4 + n;
        if (gn >= NN) continue;
        float2 rq = make_float2(acc[n][0].x + bQ.x, acc[n][0].y + bQ.y);
        float2 rk = make_float2(acc[n][1].x + bK.x, acc[n][1].y + bK.y);
        float2 rv = make_float2(acc[n][2].x + bV.x, acc[n][2].y + bV.y);
        float2 rs = make_float2(acc[n][3].x + bS.x, acc[n][3].y + bS.y);
        *reinterpret_cast<float2*>(&g_Q[gn * 64 + colp])        = rq;
        *reinterpret_cast<float2*>(&g_KV[gn * 128 + colp])      = rk;
        *reinterpret_cast<float2*>(&g_KV[gn * 128 + 64 + colp]) = rv;
        *reinterpret_cast<float2*>(&g_S[gn * 64 + colp])        = rs;
    }
}

// ---------------- attention: warp per node, CSR gather, online softmax ----------------
__global__ __launch_bounds__(256) void attn_kernel(const float* __restrict__ We_l,
                                                   float* __restrict__ dout, int toDout)
{
    int warpId = (blockIdx.x * blockDim.x + threadIdx.x) >> 5;
    int lane = threadIdx.x & 31;
    if (warpId >= NN) return;
    int i = warpId;

    float qa = g_Q[i * 64 + lane];
    float qb = g_Q[i * 64 + 32 + lane];
    float wea = We_l[lane];
    float web = We_l[32 + lane];

    float mA = -1e30f, mB = -1e30f;
    float lA = 0.f, lB = 0.f;
    float accA = 0.f, accB = 0.f;

    int beg = g_rowptr[i], end = g_rowptr[i + 1];
#pragma unroll 2
    for (int p = beg; p < end; p++) {
        int s = g_src[p];
        float ea = g_ea[p];
        const float* kv = &g_KV[(size_t)s * 128];
        float ka = kv[lane]      + ea * wea;
        float kb = kv[32 + lane] + ea * web;
        float va = kv[64 + lane] + ea * wea;
        float vb = kv[96 + lane] + ea * web;

        float dA = qa * ka;
        float dB = qb * kb;
#pragma unroll
        for (int off = 8; off >= 1; off >>= 1) {
            dA += __shfl_xor_sync(0xffffffffu, dA, off);
            dB += __shfl_xor_sync(0xffffffffu, dB, off);
        }
        dA *= 0.25f;   // 1/sqrt(C), C=16
        dB *= 0.25f;

        float mA2 = fmaxf(mA, dA);
        float cA  = __expf(mA - mA2);
        float pA  = __expf(dA - mA2);
        accA = accA * cA + pA * va;
        lA   = lA * cA + pA;
        mA   = mA2;

        float mB2 = fmaxf(mB, dB);
        float cB  = __expf(mB - mB2);
        float pB  = __expf(dB - mB2);
        accB = accB * cB + pB * vb;
        lB   = lB * cB + pB;
        mB   = mB2;
    }

    float oA = (lA > 0.f) ? accA / lA : 0.f;
    float oB = (lB > 0.f) ? accB / lB : 0.f;
    float rA = oA + g_S[i * 64 + lane];
    float rB = oB + g_S[i * 64 + 32 + lane];
    if (toDout) {
        dout[i * 64 + lane]      = rA;
        dout[i * 64 + 32 + lane] = rB;
    } else {
        g_h[i * 64 + lane]      = rA;
        g_h[i * 64 + 32 + lane] = rB;
    }
}

// ---------------- pooling: batch is sorted -> run-length accumulate ----------------
__global__ void pool_kernel(const float* __restrict__ h, const int* __restrict__ batch) {
    // block: 64 threads (one per channel), handles 32 consecutive nodes
    int c = threadIdx.x;
    int n0 = blockIdx.x * 32;
    int cur = -1;
    float acc = 0.f;
    for (int i = 0; i < 32; i++) {
        int n = n0 + i;
        if (n >= NN) break;
        int b = batch[n];
        if (b != cur) {
            if (cur >= 0) atomicAdd(&g_pool[cur * 64 + c], acc);
            cur = b;
            acc = 0.f;
        }
        acc += h[n * 64 + c];
    }
    if (cur >= 0) atomicAdd(&g_pool[cur * 64 + c], acc);
}

__global__ void cnt_kernel(const int* __restrict__ batch) {
    int n = blockIdx.x * blockDim.x + threadIdx.x;
    if (n < NN) atomicAdd(&g_cnt[batch[n]], 1);
}

// ---------------- graph MLP head ----------------
__global__ void mlp_kernel(const float* __restrict__ W1, const float* __restrict__ b1,
                           const float* __restrict__ W2, const float* __restrict__ b2,
                           const float* __restrict__ W3, const float* __restrict__ b3,
                           float* __restrict__ out)
{
    int g = blockIdx.x;
    int t = threadIdx.x; // 128
    __shared__ float gsh[64], h1[64], h2[16];
    if (t < 64) {
        float c = fmaxf((float)g_cnt[g], 1.f);
        gsh[t] = g_pool[g * 64 + t] / c;
    }
    __syncthreads();
    if (t < 64) {
        float a = b1[t];
#pragma unroll 8
        for (int d = 0; d < 64; d++) a = fmaf(gsh[d], W1[d * 64 + t], a);
        h1[t] = fmaxf(a, 0.f);
    }
    __syncthreads();
    if (t < 16) {
        float a = b2[t];
#pragma unroll 8
        for (int d = 0; d < 64; d++) a = fmaf(h1[d], W2[d * 16 + t], a);
        h2[t] = fmaxf(a, 0.f);
    }
    __syncthreads();
    {
        float a = b3[t];
#pragma unroll
        for (int d = 0; d < 16; d++) a = fmaf(h2[d], W3[d * 128 + t], a);
        out[g * 128 + t] = a;
    }
}

// ---------------- launch ----------------
extern "C" void kernel_launch(void* const* d_in, const int* in_sizes, int n_in,
                              void* d_out, int out_size)
{
    // Resolve input ordering by size probe (edge_index has 2*E elements).
    const int* ei;
    const int* batch;
    int iW;
    if (in_sizes[2] == 2 * EE) {          // dict order: x, ea, edge_index, batch, Wq...
        ei    = (const int*)d_in[2];
        batch = (const int*)d_in[3];
        iW = 4;
    } else {                               // signature order: x, ea, Wq..., edge_index, batch
        ei    = (const int*)d_in[17];
        batch = (const int*)d_in[18];
        iW = 2;
    }
    const float* x    = (const float*)d_in[0];
    const float* ea   = (const float*)d_in[1];
    const float* Wq   = (const float*)d_in[iW + 0];
    const float* bq   = (const float*)d_in[iW + 1];
    const float* Wk   = (const float*)d_in[iW + 2];
    const float* bk   = (const float*)d_in[iW + 3];
    const float* Wv   = (const float*)d_in[iW + 4];
    const float* bv   = (const float*)d_in[iW + 5];
    const float* We   = (const float*)d_in[iW + 6];
    const float* Wsk  = (const float*)d_in[iW + 7];
    const float* bsk  = (const float*)d_in[iW + 8];
    const float* W1   = (const float*)d_in[iW + 9];
    const float* b1   = (const float*)d_in[iW + 10];
    const float* W2   = (const float*)d_in[iW + 11];
    const float* b2   = (const float*)d_in[iW + 12];
    const float* W3   = (const float*)d_in[iW + 13];
    const float* b3   = (const float*)d_in[iW + 14];

    const int* srcIdx = ei;
    const int* dstIdx = ei + EE;
    float* out = (float*)d_out;

    static bool attr_set = false;
    if (!attr_set) {
        cudaFuncSetAttribute(gemm_qkvs, cudaFuncAttributeMaxDynamicSharedMemorySize,
                             (64 * 256 + TN * 64) * sizeof(float));
        attr_set = true;
    }

    // CSR build (per launch; reused by all 3 layers)
    zero_scratch_kernel<<<256, 256>>>();
    hist_kernel<<<(EE + 255) / 256, 256>>>(dstIdx);
    scan_kernel<<<1, 1024>>>();
    scatter_kernel<<<(EE + 255) / 256, 256>>>(srcIdx, dstIdx, ea);

    size_t smem = (64 * 256 + TN * 64) * sizeof(float);
    int gemmGrid = (NN + TN - 1) / TN;
    int attnGrid = (NN * 32 + 255) / 256;

    for (int l = 0; l < LLAYERS; l++) {
        int useX   = (l == 0) ? 1 : 0;
        int reluIn = (l == 0) ? 0 : 1;
        gemm_qkvs<<<gemmGrid, 256, smem>>>(
            x, useX, reluIn,
            Wq + l * DD * DD, bq + l * DD,
            Wk + l * DD * DD, bk + l * DD,
            Wv + l * DD * DD, bv + l * DD,
            Wsk + l * DD * DD, bsk + l * DD);
        int toDout = (l == LLAYERS - 1) ? 1 : 0;
        attn_kernel<<<attnGrid, 256>>>(We + l * DD, out, toDout);
    }

    // pool over final node embeddings (already in d_out) + MLP head
    pool_kernel<<<(NN + 31) / 32, 64>>>(out, batch);
    cnt_kernel<<<(NN + 255) / 256, 256>>>(batch);
    mlp_kernel<<<GG, 128>>>(W1, b1, W2, b2, W3, b3, out + (size_t)NN * DD);
}

// round 3
// speedup vs baseline: 1.3902x; 1.1970x over previous
#include <cuda_runtime.h>
#include <math.h>

#define NN 50000
#define EE 800000
#define LLAYERS 3
#define DD 64
#define GG 512
#define GDIM 128

// ---------------- scratch (static __device__, no allocs) ----------------
__device__ int   g_deg[NN];
__device__ int   g_fill[NN];
__device__ int   g_rowptr[NN + 1];
__device__ int2  g_edge[EE];          // packed {src, __float_as_int(ea)}
__device__ float g_Q[NN * DD];
__device__ float g_KV[NN * 2 * DD];   // per node: [0:64)=K, [64:128)=V (one 512B row)
__device__ float g_S[NN * DD];        // skip = x @ Wskip + bskip
__device__ float g_h[NN * DD];        // layer output (pre-relu)
__device__ float g_pool[GG * DD];
__device__ int   g_cnt[GG];

// ---------------- packed fp32x2 FMA (sm_100+) ----------------
__device__ __forceinline__ float2 ffma2(float2 x, float2 w, float2 a) {
    float2 r;
    asm("fma.rn.f32x2 %0, %1, %2, %3;"
        : "=l"(reinterpret_cast<unsigned long long&>(r))
        : "l"(reinterpret_cast<unsigned long long&>(x)),
          "l"(reinterpret_cast<unsigned long long&>(w)),
          "l"(reinterpret_cast<unsigned long long&>(a)));
    return r;
}

// ---------------- utility ----------------
__global__ void zero_scratch_kernel() {
    int idx = blockIdx.x * blockDim.x + threadIdx.x;
    int stride = gridDim.x * blockDim.x;
    for (int i = idx; i < NN; i += stride) { g_deg[i] = 0; g_fill[i] = 0; }
    for (int i = idx; i < GG * DD; i += stride) g_pool[i] = 0.f;
    for (int i = idx; i < GG; i += stride) g_cnt[i] = 0;
}

__global__ void hist_kernel(const int* __restrict__ dst) {
    int e = blockIdx.x * blockDim.x + threadIdx.x;
    if (e < EE) atomicAdd(&g_deg[dst[e]], 1);
}

// raking scan: 1024 threads, each owns 49 consecutive elements. ~20 barriers total.
__global__ void scan_kernel() {
    __shared__ int sh[1024];
    int t = threadIdx.x;
    const int PER = (NN + 1023) / 1024;  // 49
    int base = t * PER;
    int sum = 0;
#pragma unroll 7
    for (int i = 0; i < PER; i++) {
        int idx = base + i;
        if (idx < NN) sum += g_deg[idx];
    }
    sh[t] = sum;
    __syncthreads();
    for (int off = 1; off < 1024; off <<= 1) {
        int v = (t >= off) ? sh[t - off] : 0;
        __syncthreads();
        sh[t] += v;
        __syncthreads();
    }
    int run = sh[t] - sum;  // exclusive prefix
    for (int i = 0; i < PER; i++) {
        int idx = base + i;
        if (idx < NN) {
            g_rowptr[idx] = run;
            run += g_deg[idx];
        }
    }
    if (t == 1023) g_rowptr[NN] = sh[1023];
}

__global__ void scatter_kernel(const int* __restrict__ src, const int* __restrict__ dst,
                               const float* __restrict__ ea) {
    int e = blockIdx.x * blockDim.x + threadIdx.x;
    if (e >= EE) return;
    int d = dst[e];
    int pos = g_rowptr[d] + atomicAdd(&g_fill[d], 1);
    g_edge[pos] = make_int2(src[e], __float_as_int(ea[e]));
}

// ---------------- fused QKV+Skip projection, FFMA2 packed ----------------
// logical out cols: [0:64)=Q [64:128)=K [128:192)=V [192:256)=Skip
#define TN 32
__global__ __launch_bounds__(256) void gemm_qkvs(
    const float* __restrict__ X, int useX, int reluIn,
    const float* __restrict__ Wq, const float* __restrict__ bq,
    const float* __restrict__ Wk, const float* __restrict__ bk,
    const float* __restrict__ Wv, const float* __restrict__ bv,
    const float* __restrict__ Wsk, const float* __restrict__ bsk)
{
    extern __shared__ float sh[];
    float* Wsm = sh;                 // [64][256]
    float* Xsm = sh + 64 * 256;      // [TN][64]
    int tid = threadIdx.x;

    for (int i = tid; i < 64 * 64; i += 256) {
        int d = i >> 6, j = i & 63;
        Wsm[d * 256 + j]       = Wq[i];
        Wsm[d * 256 + 64 + j]  = Wk[i];
        Wsm[d * 256 + 128 + j] = Wv[i];
        Wsm[d * 256 + 192 + j] = Wsk[i];
    }
    int nodeBase = blockIdx.x * TN;
    for (int i = tid; i < TN * 64; i += 256) {
        int n = i >> 6, d = i & 63;
        int gn = nodeBase + n;
        float v = 0.f;
        if (gn < NN) v = useX ? X[gn * 64 + d] : g_h[gn * 64 + d];
        if (reluIn) v = fmaxf(v, 0.f);
        Xsm[n * 64 + d] = v;
    }
    __syncthreads();

    int cg = tid & 31;   // col pair base = 2*cg
    int ng = tid >> 5;   // nodes ng*4 + n
    float2 acc[4][4];
#pragma unroll
    for (int n = 0; n < 4; n++)
#pragma unroll
        for (int c = 0; c < 4; c++) acc[n][c] = make_float2(0.f, 0.f);

#pragma unroll 4
    for (int d = 0; d < 64; d++) {
        float2 w[4];
#pragma unroll
        for (int c = 0; c < 4; c++)
            w[c] = *reinterpret_cast<const float2*>(&Wsm[d * 256 + 2 * cg + 64 * c]);
#pragma unroll
        for (int n = 0; n < 4; n++) {
            float xv = Xsm[(ng * 4 + n) * 64 + d];
            float2 xx = make_float2(xv, xv);
#pragma unroll
            for (int c = 0; c < 4; c++) acc[n][c] = ffma2(xx, w[c], acc[n][c]);
        }
    }

    int colp = 2 * cg;
    float2 bQ = make_float2(bq[colp],  bq[colp + 1]);
    float2 bK = make_float2(bk[colp],  bk[colp + 1]);
    float2 bV = make_float2(bv[colp],  bv[colp + 1]);
    float2 bS = make_float2(bsk[colp], bsk[colp + 1]);
#pragma unroll
    for (int n = 0; n < 4; n++) {
        int gn = nodeBase + ng * 4 + n;
        if (gn >= NN) continue;
        float2 rq = make_float2(acc[n][0].x + bQ.x, acc[n][0].y + bQ.y);
        float2 rk = make_float2(acc[n][1].x + bK.x, acc[n][1].y + bK.y);
        float2 rv = make_float2(acc[n][2].x + bV.x, acc[n][2].y + bV.y);
        float2 rs = make_float2(acc[n][3].x + bS.x, acc[n][3].y + bS.y);
        *reinterpret_cast<float2*>(&g_Q[gn * 64 + colp])        = rq;
        *reinterpret_cast<float2*>(&g_KV[gn * 128 + colp])      = rk;
        *reinterpret_cast<float2*>(&g_KV[gn * 128 + 64 + colp]) = rv;
        *reinterpret_cast<float2*>(&g_S[gn * 64 + colp])        = rs;
    }
}

// ---------------- attention: warp per node, float2 lanes, 3-shuffle reduce ----------------
// lane l owns channels 2l, 2l+1. Head h = lanes 8h..8h+7. One LDG.64 covers all K,
// one covers all V. Online softmax state per 8-lane head group (replicated in-group).
__global__ __launch_bounds__(256) void attn_kernel(const float* __restrict__ We_l,
                                                   float* __restrict__ dout, int toDout)
{
    int warpId = (blockIdx.x * blockDim.x + threadIdx.x) >> 5;
    int lane = threadIdx.x & 31;
    if (warpId >= NN) return;
    int i = warpId;

    float2 q  = reinterpret_cast<const float2*>(g_Q + i * 64)[lane];
    float2 we = reinterpret_cast<const float2*>(We_l)[lane];

    float m = -1e30f, lsum = 0.f;
    float2 acc = make_float2(0.f, 0.f);

    int beg = g_rowptr[i], end = g_rowptr[i + 1];
    int p = beg;
    for (; p + 4 <= end; p += 4) {
        int2 ed[4];
#pragma unroll
        for (int j = 0; j < 4; j++) ed[j] = g_edge[p + j];
        float2 k[4], v[4];
#pragma unroll
        for (int j = 0; j < 4; j++) {
            const float2* kvp = reinterpret_cast<const float2*>(g_KV + (size_t)ed[j].x * 128);
            k[j] = kvp[lane];
            v[j] = kvp[32 + lane];
        }
#pragma unroll
        for (int j = 0; j < 4; j++) {
            float ea = __int_as_float(ed[j].y);
            float kx = fmaf(ea, we.x, k[j].x);
            float ky = fmaf(ea, we.y, k[j].y);
            float vx = fmaf(ea, we.x, v[j].x);
            float vy = fmaf(ea, we.y, v[j].y);
            float d = fmaf(q.x, kx, q.y * ky);
            d += __shfl_xor_sync(0xffffffffu, d, 4);
            d += __shfl_xor_sync(0xffffffffu, d, 2);
            d += __shfl_xor_sync(0xffffffffu, d, 1);
            d *= 0.25f;   // 1/sqrt(C), C=16
            float m2 = fmaxf(m, d);
            float c  = __expf(m - m2);
            float pe = __expf(d - m2);
            acc.x = acc.x * c + pe * vx;
            acc.y = acc.y * c + pe * vy;
            lsum  = lsum * c + pe;
            m = m2;
        }
    }
    for (; p < end; p++) {
        int2 ed = g_edge[p];
        const float2* kvp = reinterpret_cast<const float2*>(g_KV + (size_t)ed.x * 128);
        float2 k = kvp[lane];
        float2 v = kvp[32 + lane];
        float ea = __int_as_float(ed.y);
        float kx = fmaf(ea, we.x, k.x);
        float ky = fmaf(ea, we.y, k.y);
        float vx = fmaf(ea, we.x, v.x);
        float vy = fmaf(ea, we.y, v.y);
        float d = fmaf(q.x, kx, q.y * ky);
        d += __shfl_xor_sync(0xffffffffu, d, 4);
        d += __shfl_xor_sync(0xffffffffu, d, 2);
        d += __shfl_xor_sync(0xffffffffu, d, 1);
        d *= 0.25f;
        float m2 = fmaxf(m, d);
        float c  = __expf(m - m2);
        float pe = __expf(d - m2);
        acc.x = acc.x * c + pe * vx;
        acc.y = acc.y * c + pe * vy;
        lsum  = lsum * c + pe;
        m = m2;
    }

    float inv = (lsum > 0.f) ? 1.f / lsum : 0.f;
    float2 s = reinterpret_cast<const float2*>(g_S + i * 64)[lane];
    float2 r = make_float2(fmaf(acc.x, inv, s.x), fmaf(acc.y, inv, s.y));
    float* base = toDout ? dout : g_h;
    reinterpret_cast<float2*>(base + i * 64)[lane] = r;
}

// ---------------- pooling: batch is sorted -> run-length accumulate ----------------
__global__ void pool_kernel(const float* __restrict__ h, const int* __restrict__ batch) {
    // block: 64 threads (one per channel), handles 32 consecutive nodes
    int c = threadIdx.x;
    int n0 = blockIdx.x * 32;
    int cur = -1;
    float acc = 0.f;
    for (int i = 0; i < 32; i++) {
        int n = n0 + i;
        if (n >= NN) break;
        int b = batch[n];
        if (b != cur) {
            if (cur >= 0) atomicAdd(&g_pool[cur * 64 + c], acc);
            cur = b;
            acc = 0.f;
        }
        acc += h[n * 64 + c];
    }
    if (cur >= 0) atomicAdd(&g_pool[cur * 64 + c], acc);
}

__global__ void cnt_kernel(const int* __restrict__ batch) {
    int n = blockIdx.x * blockDim.x + threadIdx.x;
    if (n < NN) atomicAdd(&g_cnt[batch[n]], 1);
}

// ---------------- graph MLP head ----------------
__global__ void mlp_kernel(const float* __restrict__ W1, const float* __restrict__ b1,
                           const float* __restrict__ W2, const float* __restrict__ b2,
                           const float* __restrict__ W3, const float* __restrict__ b3,
                           float* __restrict__ out)
{
    int g = blockIdx.x;
    int t = threadIdx.x; // 128
    __shared__ float gsh[64], h1[64], h2[16];
    if (t < 64) {
        float c = fmaxf((float)g_cnt[g], 1.f);
        gsh[t] = g_pool[g * 64 + t] / c;
    }
    __syncthreads();
    if (t < 64) {
        float a = b1[t];
#pragma unroll 8
        for (int d = 0; d < 64; d++) a = fmaf(gsh[d], W1[d * 64 + t], a);
        h1[t] = fmaxf(a, 0.f);
    }
    __syncthreads();
    if (t < 16) {
        float a = b2[t];
#pragma unroll 8
        for (int d = 0; d < 64; d++) a = fmaf(h1[d], W2[d * 16 + t], a);
        h2[t] = fmaxf(a, 0.f);
    }
    __syncthreads();
    {
        float a = b3[t];
#pragma unroll
        for (int d = 0; d < 16; d++) a = fmaf(h2[d], W3[d * 128 + t], a);
        out[g * 128 + t] = a;
    }
}

// ---------------- launch ----------------
extern "C" void kernel_launch(void* const* d_in, const int* in_sizes, int n_in,
                              void* d_out, int out_size)
{
    // Resolve input ordering by size probe (edge_index has 2*E elements).
    const int* ei;
    const int* batch;
    int iW;
    if (in_sizes[2] == 2 * EE) {          // dict order: x, ea, edge_index, batch, Wq...
        ei    = (const int*)d_in[2];
        batch = (const int*)d_in[3];
        iW = 4;
    } else {                               // signature order: x, ea, Wq..., edge_index, batch
        ei    = (const int*)d_in[17];
        batch = (const int*)d_in[18];
        iW = 2;
    }
    const float* x    = (const float*)d_in[0];
    const float* ea   = (const float*)d_in[1];
    const float* Wq   = (const float*)d_in[iW + 0];
    const float* bq   = (const float*)d_in[iW + 1];
    const float* Wk   = (const float*)d_in[iW + 2];
    const float* bk   = (const float*)d_in[iW + 3];
    const float* Wv   = (const float*)d_in[iW + 4];
    const float* bv   = (const float*)d_in[iW + 5];
    const float* We   = (const float*)d_in[iW + 6];
    const float* Wsk  = (const float*)d_in[iW + 7];
    const float* bsk  = (const float*)d_in[iW + 8];
    const float* W1   = (const float*)d_in[iW + 9];
    const float* b1   = (const float*)d_in[iW + 10];
    const float* W2   = (const float*)d_in[iW + 11];
    const float* b2   = (const float*)d_in[iW + 12];
    const float* W3   = (const float*)d_in[iW + 13];
    const float* b3   = (const float*)d_in[iW + 14];

    const int* srcIdx = ei;
    const int* dstIdx = ei + EE;
    float* out = (float*)d_out;

    static bool attr_set = false;
    if (!attr_set) {
        cudaFuncSetAttribute(gemm_qkvs, cudaFuncAttributeMaxDynamicSharedMemorySize,
                             (64 * 256 + TN * 64) * sizeof(float));
        attr_set = true;
    }

    // CSR build (per launch; reused by all 3 layers)
    zero_scratch_kernel<<<256, 256>>>();
    hist_kernel<<<(EE + 255) / 256, 256>>>(dstIdx);
    scan_kernel<<<1, 1024>>>();
    scatter_kernel<<<(EE + 255) / 256, 256>>>(srcIdx, dstIdx, ea);

    size_t smem = (64 * 256 + TN * 64) * sizeof(float);
    int gemmGrid = (NN + TN - 1) / TN;
    int attnGrid = (NN * 32 + 255) / 256;

    for (int l = 0; l < LLAYERS; l++) {
        int useX   = (l == 0) ? 1 : 0;
        int reluIn = (l == 0) ? 0 : 1;
        gemm_qkvs<<<gemmGrid, 256, smem>>>(
            x, useX, reluIn,
            Wq + l * DD * DD, bq + l * DD,
            Wk + l * DD * DD, bk + l * DD,
            Wv + l * DD * DD, bv + l * DD,
            Wsk + l * DD * DD, bsk + l * DD);
        int toDout = (l == LLAYERS - 1) ? 1 : 0;
        attn_kernel<<<attnGrid, 256>>>(We + l * DD, out, toDout);
    }

    // pool over final node embeddings (already in d_out) + MLP head
    pool_kernel<<<(NN + 31) / 32, 64>>>(out, batch);
    cnt_kernel<<<(NN + 255) / 256, 256>>>(batch);
    mlp_kernel<<<GG, 128>>>(W1, b1, W2, b2, W3, b3, out + (size_t)NN * DD);
}